// round 10
// baseline (speedup 1.0000x reference)
#include <cuda_runtime.h>
#include <math.h>

#define BATCH 64
#define SEQ   512
#define EMB   512
#define HID   1024
#define BH    (BATCH * HID)        // 65536
#define SBH   (SEQ * BH)           // 33554432
#define KSLICES 8
#define NBLOCKS 128                // 16 h-tiles (64h) x 8 k-slices (128k)

#define AS_STRIDE 68               // padded k-major a-slice row (floats)
#define RNN_SMEM  ((128 * 64 + 128 * AS_STRIDE) * 4)   // Ws + As = 67584 B

typedef unsigned long long u64;

// Per-step K-split partials: [KSLICES][BATCH][HID] = 2 MB
__device__ float g_partial[KSLICES * BH];
// Distributed barrier counters: 4 counters, 256B apart
__device__ unsigned g_cnt[256];

// ---------------- packed fp32x2 helpers (sm_103a) ---------------------------
__device__ __forceinline__ u64 pkdup(float x) {
    u64 r; asm("mov.b64 %0, {%1, %1};" : "=l"(r) : "f"(x)); return r;
}
__device__ __forceinline__ void fma2(u64& d, u64 a, u64 b) {
    asm("fma.rn.f32x2 %0, %1, %2, %0;" : "+l"(d) : "l"(a), "l"(b));
}
__device__ __forceinline__ float2 un2(u64 v) {
    float2 f; asm("mov.b64 {%0, %1}, %2;" : "=f"(f.x), "=f"(f.y) : "l"(v));
    return f;
}

// ---------------------------------------------------------------------------
// Distributed grid barrier: release-add arrive on counter (bi&3); waiters
// acquire-load all 4 counters until each reaches 32*phase.
// ---------------------------------------------------------------------------
__device__ __forceinline__ void gridbar(unsigned& phase) {
    phase++;
    const unsigned target = phase * 32u;
    __syncthreads();
    if (threadIdx.x == 0) {
        unsigned* my = &g_cnt[(blockIdx.x & 3) * 64];
        asm volatile("red.release.gpu.global.add.u32 [%0], %1;"
                     :: "l"(my), "r"(1u) : "memory");
        unsigned c0, c1, c2, c3;
        do {
            asm volatile("ld.acquire.gpu.global.u32 %0, [%1];" : "=r"(c0) : "l"(&g_cnt[0]));
            asm volatile("ld.acquire.gpu.global.u32 %0, [%1];" : "=r"(c1) : "l"(&g_cnt[64]));
            asm volatile("ld.acquire.gpu.global.u32 %0, [%1];" : "=r"(c2) : "l"(&g_cnt[128]));
            asm volatile("ld.acquire.gpu.global.u32 %0, [%1];" : "=r"(c3) : "l"(&g_cnt[192]));
        } while (c0 < target || c1 < target || c2 < target || c3 < target);
    }
    __syncthreads();
}

// ---------------------------------------------------------------------------
// Kernel 1: xproj[s][b][h] = sum_e X[b][s][e] * Wax[h][e] + ba[h]
// 128x128 tile, BK=16, 256 threads, 8x8 per thread, f32x2 packed.
// ---------------------------------------------------------------------------
__global__ __launch_bounds__(256) void xproj_kernel(
    const float* __restrict__ X, const float* __restrict__ Wax,
    const float* __restrict__ ba, float* __restrict__ out)
{
    __shared__ float As[16][128];
    __shared__ float Bs[16][128];

    const int tid = threadIdx.x;
    const int r0 = blockIdx.x * 128;
    const int h0 = blockIdx.y * 128;

    const int lr = tid >> 1;           // 0..127
    const int lk = (tid & 1) * 8;      // 0 or 8
    const int r  = r0 + lr;
    const float* Aptr = X + (size_t)(r & (BATCH - 1)) * (SEQ * EMB)
                          + (size_t)(r >> 6) * EMB + lk;
    const float* Bptr = Wax + (size_t)(h0 + lr) * EMB + lk;

    const int tm0 = (tid >> 4) * 4;
    const int tn0 = (tid & 15) * 4;

    u64 acc[8][4];
#pragma unroll
    for (int i = 0; i < 8; i++)
#pragma unroll
        for (int p = 0; p < 4; p++) acc[i][p] = 0ull;

    for (int k0 = 0; k0 < EMB; k0 += 16) {
        float4 a0 = *(const float4*)(Aptr + k0);
        float4 a1 = *(const float4*)(Aptr + k0 + 4);
        float4 b0 = *(const float4*)(Bptr + k0);
        float4 b1 = *(const float4*)(Bptr + k0 + 4);
        As[lk + 0][lr] = a0.x; As[lk + 1][lr] = a0.y;
        As[lk + 2][lr] = a0.z; As[lk + 3][lr] = a0.w;
        As[lk + 4][lr] = a1.x; As[lk + 5][lr] = a1.y;
        As[lk + 6][lr] = a1.z; As[lk + 7][lr] = a1.w;
        Bs[lk + 0][lr] = b0.x; Bs[lk + 1][lr] = b0.y;
        Bs[lk + 2][lr] = b0.z; Bs[lk + 3][lr] = b0.w;
        Bs[lk + 4][lr] = b1.x; Bs[lk + 5][lr] = b1.y;
        Bs[lk + 6][lr] = b1.z; Bs[lk + 7][lr] = b1.w;
        __syncthreads();

#pragma unroll
        for (int k = 0; k < 16; k++) {
            float4 av0 = *(const float4*)&As[k][tm0];
            float4 av1 = *(const float4*)&As[k][tm0 + 64];
            ulonglong2 wA = *(const ulonglong2*)&Bs[k][tn0];
            ulonglong2 wB = *(const ulonglong2*)&Bs[k][tn0 + 64];
            float ar[8] = {av0.x, av0.y, av0.z, av0.w, av1.x, av1.y, av1.z, av1.w};
#pragma unroll
            for (int i = 0; i < 8; i++) {
                u64 ai = pkdup(ar[i]);
                fma2(acc[i][0], ai, wA.x);
                fma2(acc[i][1], ai, wA.y);
                fma2(acc[i][2], ai, wB.x);
                fma2(acc[i][3], ai, wB.y);
            }
        }
        __syncthreads();
    }

    float bav[8];
#pragma unroll
    for (int j = 0; j < 4; j++) {
        bav[j]     = ba[h0 + tn0 + j];
        bav[4 + j] = ba[h0 + tn0 + 64 + j];
    }
#pragma unroll
    for (int gi = 0; gi < 2; gi++) {
#pragma unroll
        for (int ii = 0; ii < 4; ii++) {
            int i = gi * 4 + ii;
            int row = r0 + tm0 + gi * 64 + ii;
            float* o = out + (size_t)row * HID + h0;
            float2 p0 = un2(acc[i][0]), p1 = un2(acc[i][1]);
            float2 p2 = un2(acc[i][2]), p3 = un2(acc[i][3]);
            *(float4*)(o + tn0)      = make_float4(p0.x + bav[0], p0.y + bav[1],
                                                   p1.x + bav[2], p1.y + bav[3]);
            *(float4*)(o + tn0 + 64) = make_float4(p2.x + bav[4], p2.y + bav[5],
                                                   p3.x + bav[6], p3.y + bav[7]);
        }
    }
}

// ---------------------------------------------------------------------------
// Kernel 2: persistent recurrence. 128 CTAs x 256 threads.
// CTA bi: h-tile ht=bi>>3 (64 h), k-slice ks=bi&7 (128 k).
// Dynamic smem: Ws[128k][64h] (32 KB) + As[128k][68pad] (34 KB), both
// resident; 1 syncthreads + 2 gridbars per step. b-pair f32x2 packing:
// a-pairs load pre-packed from k-major As, W dup'd 2x per k.
// ---------------------------------------------------------------------------
__global__ __launch_bounds__(256) void rnn_persistent(
    const float* __restrict__ Waa, float* __restrict__ outs, int write_hidden)
{
    extern __shared__ float sm[];
    float* Ws  = sm;                   // [128][64]
    float* Asb = sm + 128 * 64;        // [128][AS_STRIDE]

    const int tid = threadIdx.x;
    const int bi  = blockIdx.x;
    const int ht  = bi >> 3;           // 0..15
    const int ks  = bi & 7;            // 0..7
    const int h0  = ht * 64;
    const int k0  = ks * 128;

    // Load W slice once: Ws[k][h] = Waa[h0+h][k0+k]
    {
        const int h  = tid & 63;
        const int kg = tid >> 6;       // 0..3 -> k base kg*32
        const float* wrow = Waa + (size_t)(h0 + h) * HID + k0 + kg * 32;
#pragma unroll
        for (int j = 0; j < 8; j++) {
            float4 w = *(const float4*)(wrow + j * 4);
            int k = kg * 32 + j * 4;
            Ws[(k + 0) * 64 + h] = w.x; Ws[(k + 1) * 64 + h] = w.y;
            Ws[(k + 2) * 64 + h] = w.z; Ws[(k + 3) * 64 + h] = w.w;
        }
    }
    __syncthreads();

    const int l   = tid & 31;
    const int wb0 = (tid >> 5) * 8;    // warp's 8 batch rows
    const int hh  = 2 * l;             // h-pair within 64
    const int sb  = tid >> 2;          // staging b 0..63
    const int skg = (tid & 3) * 4;     // staging k base

    unsigned phase = 0;

    for (int s = 0; s < SEQ; s++) {
        if (s > 0) {
            // ---- stage a_{s-1} [64b x 128k] into k-major As (L2, bypass L1)
            const float* src = outs + (size_t)(s - 1) * BH
                             + (size_t)sb * HID + k0 + skg;
            float4 t4[8];
#pragma unroll
            for (int j = 0; j < 8; j++)
                t4[j] = __ldcg((const float4*)(src + j * 16));
#pragma unroll
            for (int j = 0; j < 8; j++) {
                int k = skg + j * 16;
                Asb[(k + 0) * AS_STRIDE + sb] = t4[j].x;
                Asb[(k + 1) * AS_STRIDE + sb] = t4[j].y;
                Asb[(k + 2) * AS_STRIDE + sb] = t4[j].z;
                Asb[(k + 3) * AS_STRIDE + sb] = t4[j].w;
            }
            __syncthreads();

            // ---- compute: acc[4 b-pairs][2 h]  (b-pairs packed in u64)
            u64 acc[4][2];
#pragma unroll
            for (int i = 0; i < 4; i++) { acc[i][0] = 0ull; acc[i][1] = 0ull; }

#pragma unroll 8
            for (int k = 0; k < 128; k++) {
                const float* arow = Asb + k * AS_STRIDE + wb0;   // warp-uniform
                ulonglong2 aA = *(const ulonglong2*)arow;        // (b0,b1),(b2,b3)
                ulonglong2 aB = *(const ulonglong2*)(arow + 4);  // (b4,b5),(b6,b7)
                float2 wv = *(const float2*)(Ws + k * 64 + hh);
                u64 w0 = pkdup(wv.x);
                u64 w1 = pkdup(wv.y);
                fma2(acc[0][0], aA.x, w0); fma2(acc[0][1], aA.x, w1);
                fma2(acc[1][0], aA.y, w0); fma2(acc[1][1], aA.y, w1);
                fma2(acc[2][0], aB.x, w0); fma2(acc[2][1], aB.x, w1);
                fma2(acc[3][0], aB.y, w0); fma2(acc[3][1], aB.y, w1);
            }

            // ---- write partials: g_partial[ks][b][h0+hh .. +1]
            float* gp = g_partial + (size_t)ks * BH + (size_t)wb0 * HID + h0 + hh;
#pragma unroll
            for (int bp = 0; bp < 4; bp++) {
                float2 e = un2(acc[bp][0]);   // h=hh   for b even/odd
                float2 o = un2(acc[bp][1]);   // h=hh+1
                *(float2*)(gp + (size_t)(2 * bp)     * HID) = make_float2(e.x, o.x);
                *(float2*)(gp + (size_t)(2 * bp + 1) * HID) = make_float2(e.y, o.y);
            }
            gridbar(phase);
        }

        // ---- phase2: out[s] = tanh(xproj + sum_p partial), 512 el per CTA
        if (tid < 128) {
            const size_t e4 = (size_t)bi * 128 + tid;
            float4* o4 = (float4*)outs + (size_t)s * (BH / 4) + e4;
            float4 v = *o4;
            if (s > 0) {
                const float4* p4 = (const float4*)g_partial + e4;
#pragma unroll
                for (int p = 0; p < KSLICES; p++) {
                    float4 q = __ldcg(p4 + (size_t)p * (BH / 4));
                    v.x += q.x; v.y += q.y; v.z += q.z; v.w += q.w;
                }
            }
            v.x = tanhf(v.x); v.y = tanhf(v.y);
            v.z = tanhf(v.z); v.w = tanhf(v.w);
            *o4 = v;
        }
        gridbar(phase);
    }

    // Final hidden = outputs[SEQ-1] appended after outputs region
    if (write_hidden) {
#pragma unroll
        for (int t = 0; t < 2; t++) {
            int idx = bi * 512 + t * 256 + tid;
            outs[(size_t)SBH + idx] = outs[(size_t)(SEQ - 1) * BH + idx];
        }
    }
}

// ---------------------------------------------------------------------------
// Launch. Inputs: X [B,S,E] f32, W_ax [H,E] f32, W_aa [H,H] f32, b_a [H] f32.
// Output: outputs [S,B,H] then hidden [B,H].
// ---------------------------------------------------------------------------
extern "C" void kernel_launch(void* const* d_in, const int* in_sizes, int n_in,
                              void* d_out, int out_size) {
    (void)in_sizes; (void)n_in;
    const float* X   = (const float*)d_in[0];
    const float* Wax = (const float*)d_in[1];
    const float* Waa = (const float*)d_in[2];
    const float* ba  = (const float*)d_in[3];
    float* out = (float*)d_out;

    cudaFuncSetAttribute(rnn_persistent,
                         cudaFuncAttributeMaxDynamicSharedMemorySize, RNN_SMEM);

    void* cntp = nullptr;
    cudaGetSymbolAddress(&cntp, g_cnt);
    cudaMemsetAsync(cntp, 0, 256 * sizeof(unsigned), 0);

    dim3 g1((SEQ * BATCH) / 128, HID / 128);
    xproj_kernel<<<g1, 256>>>(X, Wax, ba, out);

    int write_hidden = (out_size >= (int)(SBH + BH)) ? 1 : 0;
    rnn_persistent<<<NBLOCKS, 256, RNN_SMEM>>>(Waa, out, write_hidden);
}

// round 11
// speedup vs baseline: 1.2917x; 1.2917x over previous
#include <cuda_runtime.h>
#include <math.h>

#define BATCH 64
#define SEQ   512
#define EMB   512
#define HID   1024
#define BH    (BATCH * HID)        // 65536
#define SBH   (SEQ * BH)           // 33554432
#define KSLICES 8
#define NBLOCKS 128                // 16 h-tiles (64h) x 8 k-slices (128k)

#define AS_STRIDE 68
#define RNN_SMEM  ((128 * 64 + 128 * AS_STRIDE) * 4)   // Ws + As = 67584 B

typedef unsigned long long u64;

// Per-step K-split partials: [KSLICES][BATCH][HID] = 2 MB
__device__ float g_partial[KSLICES * BH];
// Group sync counters: [0..511] partial-ready (8 groups x 64-word stride),
//                      [512..1023] a-ready. Zeroed per launch.
__device__ unsigned g_sync[1024];

// ---------------- packed fp32x2 helpers (sm_103a) ---------------------------
__device__ __forceinline__ u64 pkdup(float x) {
    u64 r; asm("mov.b64 %0, {%1, %1};" : "=l"(r) : "f"(x)); return r;
}
__device__ __forceinline__ void fma2(u64& d, u64 a, u64 b) {
    asm("fma.rn.f32x2 %0, %1, %2, %0;" : "+l"(d) : "l"(a), "l"(b));
}
__device__ __forceinline__ float2 un2(u64 v) {
    float2 f; asm("mov.b64 {%0, %1}, %2;" : "=f"(f.x), "=f"(f.y) : "l"(v));
    return f;
}
__device__ __forceinline__ unsigned ldacq(const unsigned* p) {
    unsigned v;
    asm volatile("ld.acquire.gpu.global.u32 %0, [%1];" : "=r"(v) : "l"(p));
    return v;
}
__device__ __forceinline__ void redrel(unsigned* p) {
    asm volatile("red.release.gpu.global.add.u32 [%0], %1;"
                 :: "l"(p), "r"(1u) : "memory");
}

// ---------------------------------------------------------------------------
// Kernel 1: xproj[s][b][h] = sum_e X[b][s][e] * Wax[h][e] + ba[h]  (as R10)
// ---------------------------------------------------------------------------
__global__ __launch_bounds__(256) void xproj_kernel(
    const float* __restrict__ X, const float* __restrict__ Wax,
    const float* __restrict__ ba, float* __restrict__ out)
{
    __shared__ float As[16][128];
    __shared__ float Bs[16][128];

    const int tid = threadIdx.x;
    const int r0 = blockIdx.x * 128;
    const int h0 = blockIdx.y * 128;

    const int lr = tid >> 1;
    const int lk = (tid & 1) * 8;
    const int r  = r0 + lr;
    const float* Aptr = X + (size_t)(r & (BATCH - 1)) * (SEQ * EMB)
                          + (size_t)(r >> 6) * EMB + lk;
    const float* Bptr = Wax + (size_t)(h0 + lr) * EMB + lk;

    const int tm0 = (tid >> 4) * 4;
    const int tn0 = (tid & 15) * 4;

    u64 acc[8][4];
#pragma unroll
    for (int i = 0; i < 8; i++)
#pragma unroll
        for (int p = 0; p < 4; p++) acc[i][p] = 0ull;

    for (int k0 = 0; k0 < EMB; k0 += 16) {
        float4 a0 = *(const float4*)(Aptr + k0);
        float4 a1 = *(const float4*)(Aptr + k0 + 4);
        float4 b0 = *(const float4*)(Bptr + k0);
        float4 b1 = *(const float4*)(Bptr + k0 + 4);
        As[lk + 0][lr] = a0.x; As[lk + 1][lr] = a0.y;
        As[lk + 2][lr] = a0.z; As[lk + 3][lr] = a0.w;
        As[lk + 4][lr] = a1.x; As[lk + 5][lr] = a1.y;
        As[lk + 6][lr] = a1.z; As[lk + 7][lr] = a1.w;
        Bs[lk + 0][lr] = b0.x; Bs[lk + 1][lr] = b0.y;
        Bs[lk + 2][lr] = b0.z; Bs[lk + 3][lr] = b0.w;
        Bs[lk + 4][lr] = b1.x; Bs[lk + 5][lr] = b1.y;
        Bs[lk + 6][lr] = b1.z; Bs[lk + 7][lr] = b1.w;
        __syncthreads();

#pragma unroll
        for (int k = 0; k < 16; k++) {
            float4 av0 = *(const float4*)&As[k][tm0];
            float4 av1 = *(const float4*)&As[k][tm0 + 64];
            ulonglong2 wA = *(const ulonglong2*)&Bs[k][tn0];
            ulonglong2 wB = *(const ulonglong2*)&Bs[k][tn0 + 64];
            float ar[8] = {av0.x, av0.y, av0.z, av0.w, av1.x, av1.y, av1.z, av1.w};
#pragma unroll
            for (int i = 0; i < 8; i++) {
                u64 ai = pkdup(ar[i]);
                fma2(acc[i][0], ai, wA.x);
                fma2(acc[i][1], ai, wA.y);
                fma2(acc[i][2], ai, wB.x);
                fma2(acc[i][3], ai, wB.y);
            }
        }
        __syncthreads();
    }

    float bav[8];
#pragma unroll
    for (int j = 0; j < 4; j++) {
        bav[j]     = ba[h0 + tn0 + j];
        bav[4 + j] = ba[h0 + tn0 + 64 + j];
    }
#pragma unroll
    for (int gi = 0; gi < 2; gi++) {
#pragma unroll
        for (int ii = 0; ii < 4; ii++) {
            int i = gi * 4 + ii;
            int row = r0 + tm0 + gi * 64 + ii;
            float* o = out + (size_t)row * HID + h0;
            float2 p0 = un2(acc[i][0]), p1 = un2(acc[i][1]);
            float2 p2 = un2(acc[i][2]), p3 = un2(acc[i][3]);
            *(float4*)(o + tn0)      = make_float4(p0.x + bav[0], p0.y + bav[1],
                                                   p1.x + bav[2], p1.y + bav[3]);
            *(float4*)(o + tn0 + 64) = make_float4(p2.x + bav[4], p2.y + bav[5],
                                                   p3.x + bav[6], p3.y + bav[7]);
        }
    }
}

// ---------------------------------------------------------------------------
// Kernel 2: persistent recurrence with GROUP-LOCAL sync (no grid barrier).
// CTA bi: h-tile ht=bi>>3 (64 h), k-slice ks=bi&7 (128 k). Group g=ht>>1
// (8 groups of 16 CTAs; group g owns h-range [128g,128g+128)).
// Counters (per group, monotonically += 16 per step):
//   cp[g]: group-g partials for step s all written   (value 16*s after step s)
//   ca[g]: group-g slice of a_s written              (value 16*(s+1) after s)
// Step s>=1 for CTA (ht,ks), g=ht>>1:
//   prefetch xp; wait ca[ks]>=16s (stage dep) & ca[g]>=16s (partial overwrite
//   safety); stage a_{s-1}[.][k-slice]; compute partials; STG; release cp[g];
//   wait cp[g]>=16s; phase2 for own group's h-range slice: tanh(xp+sum),
//   STG a_s; release ca[g].
// ---------------------------------------------------------------------------
__global__ __launch_bounds__(256) void rnn_persistent(
    const float* __restrict__ Waa, float* __restrict__ outs, int write_hidden)
{
    extern __shared__ float sm[];
    float* Ws  = sm;                   // [128][64]
    float* Asb = sm + 128 * 64;        // [128][AS_STRIDE]

    const int tid = threadIdx.x;
    const int bi  = blockIdx.x;
    const int ht  = bi >> 3;           // 0..15
    const int ks  = bi & 7;            // 0..7
    const int g   = ht >> 1;           // own group 0..7
    const int h0  = ht * 64;
    const int k0  = ks * 128;

    unsigned* cp     = g_sync + g * 64;
    unsigned* ca_own = g_sync + 512 + g * 64;
    unsigned* ca_ks  = g_sync + 512 + ks * 64;

    // Load W slice once: Ws[k][h] = Waa[h0+h][k0+k]
    {
        const int h  = tid & 63;
        const int kg = tid >> 6;
        const float* wrow = Waa + (size_t)(h0 + h) * HID + k0 + kg * 32;
#pragma unroll
        for (int j = 0; j < 8; j++) {
            float4 w = *(const float4*)(wrow + j * 4);
            int k = kg * 32 + j * 4;
            Ws[(k + 0) * 64 + h] = w.x; Ws[(k + 1) * 64 + h] = w.y;
            Ws[(k + 2) * 64 + h] = w.z; Ws[(k + 3) * 64 + h] = w.w;
        }
    }
    __syncthreads();

    // compute-tile mapping
    const int l   = tid & 31;
    const int wb0 = (tid >> 5) * 8;
    const int hh  = 2 * l;
    // staging mapping
    const int sb  = tid >> 2;
    const int skg = (tid & 3) * 4;
    // phase2 mapping: group-local CTA index cg, float2 per thread
    const int cg  = ((ht & 1) << 3) | ks;          // 0..15
    const int e   = cg * 256 + tid;                // 0..4095
    const size_t p2off = (size_t)(e >> 6) * HID + g * 128 + (e & 63) * 2;

    for (int s = 0; s < SEQ; s++) {
        // prefetch own xproj element (no writer until our own phase2 below)
        float2 xp = *(const float2*)(outs + (size_t)s * BH + p2off);

        if (s > 0) {
            // wait: a_{s-1}[.][k-slice ks] ready AND own-group phase2 of s-1
            // done (so overwriting step-(s-1) partials is safe)
            if (tid == 0) {
                const unsigned t = 16u * (unsigned)s;
                while (ldacq(ca_ks) < t) { }
                if (ca_own != ca_ks) while (ldacq(ca_own) < t) { }
            }
            __syncthreads();

            // ---- stage a_{s-1} [64b x 128k] into k-major smem (L2 path)
            const float* src = outs + (size_t)(s - 1) * BH
                             + (size_t)sb * HID + k0 + skg;
            float4 t4[8];
#pragma unroll
            for (int j = 0; j < 8; j++)
                t4[j] = __ldcg((const float4*)(src + j * 16));
#pragma unroll
            for (int j = 0; j < 8; j++) {
                int k = skg + j * 16;
                Asb[(k + 0) * AS_STRIDE + sb] = t4[j].x;
                Asb[(k + 1) * AS_STRIDE + sb] = t4[j].y;
                Asb[(k + 2) * AS_STRIDE + sb] = t4[j].z;
                Asb[(k + 3) * AS_STRIDE + sb] = t4[j].w;
            }
            __syncthreads();

            // ---- compute acc[4 b-pairs][2 h]
            u64 acc[4][2];
#pragma unroll
            for (int i = 0; i < 4; i++) { acc[i][0] = 0ull; acc[i][1] = 0ull; }

#pragma unroll 8
            for (int k = 0; k < 128; k++) {
                const float* arow = Asb + k * AS_STRIDE + wb0;
                ulonglong2 aA = *(const ulonglong2*)arow;
                ulonglong2 aB = *(const ulonglong2*)(arow + 4);
                float2 wv = *(const float2*)(Ws + k * 64 + hh);
                u64 w0 = pkdup(wv.x);
                u64 w1 = pkdup(wv.y);
                fma2(acc[0][0], aA.x, w0); fma2(acc[0][1], aA.x, w1);
                fma2(acc[1][0], aA.y, w0); fma2(acc[1][1], aA.y, w1);
                fma2(acc[2][0], aB.x, w0); fma2(acc[2][1], aB.x, w1);
                fma2(acc[3][0], aB.y, w0); fma2(acc[3][1], aB.y, w1);
            }

            // ---- write partials: g_partial[ks][b][h0+hh..+1]
            float* gp = g_partial + (size_t)ks * BH + (size_t)wb0 * HID + h0 + hh;
#pragma unroll
            for (int bp = 0; bp < 4; bp++) {
                float2 ev = un2(acc[bp][0]);
                float2 ov = un2(acc[bp][1]);
                *(float2*)(gp + (size_t)(2 * bp)     * HID) = make_float2(ev.x, ov.x);
                *(float2*)(gp + (size_t)(2 * bp + 1) * HID) = make_float2(ev.y, ov.y);
            }
            __syncthreads();
            if (tid == 0) {
                redrel(cp);
                // wait all 16 group partials for step s
                const unsigned t = 16u * (unsigned)s;
                while (ldacq(cp) < t) { }
            }
            __syncthreads();
        }

        // ---- phase2: own group's h-range slice, float2 per thread
        {
            float2 v = xp;
            if (s > 0) {
                const float* pp = g_partial + p2off;
#pragma unroll
                for (int p = 0; p < KSLICES; p++) {
                    float2 q = __ldcg((const float2*)(pp + (size_t)p * BH));
                    v.x += q.x; v.y += q.y;
                }
            }
            v.x = tanhf(v.x); v.y = tanhf(v.y);
            *(float2*)(outs + (size_t)s * BH + p2off) = v;
            if (write_hidden && s == SEQ - 1)
                *(float2*)(outs + (size_t)SBH + p2off) = v;
        }
        __syncthreads();
        if (tid == 0) redrel(ca_own);
        // no block-wide wait here: next iteration's poll covers it
    }
}

// ---------------------------------------------------------------------------
// Launch. Inputs: X [B,S,E] f32, W_ax [H,E] f32, W_aa [H,H] f32, b_a [H] f32.
// Output: outputs [S,B,H] then hidden [B,H].
// ---------------------------------------------------------------------------
extern "C" void kernel_launch(void* const* d_in, const int* in_sizes, int n_in,
                              void* d_out, int out_size) {
    (void)in_sizes; (void)n_in;
    const float* X   = (const float*)d_in[0];
    const float* Wax = (const float*)d_in[1];
    const float* Waa = (const float*)d_in[2];
    const float* ba  = (const float*)d_in[3];
    float* out = (float*)d_out;

    cudaFuncSetAttribute(rnn_persistent,
                         cudaFuncAttributeMaxDynamicSharedMemorySize, RNN_SMEM);

    void* sp = nullptr;
    cudaGetSymbolAddress(&sp, g_sync);
    cudaMemsetAsync(sp, 0, 1024 * sizeof(unsigned), 0);

    dim3 g1((SEQ * BATCH) / 128, HID / 128);
    xproj_kernel<<<g1, 256>>>(X, Wax, ba, out);

    int write_hidden = (out_size >= (int)(SBH + BH)) ? 1 : 0;
    rnn_persistent<<<NBLOCKS, 256, RNN_SMEM>>>(Waa, out, write_hidden);
}